// round 11
// baseline (speedup 1.0000x reference)
#include <cuda_runtime.h>

#define NB    64
#define NV    4096
#define NFEAT 16
#define NA    8
#define NP    16
#define NOUT  16
#define S1    16                 // blocks per batch
#define CH    256                // vertices per block (phase A)
#define GRID1 (NB * S1)          // 1024

// Per-(b,split) partials; slot owned exclusively -> no zeroing kernel.
__device__ float    g_part[GRID1 * 128];
// Per-vertex edge weights exported in phase A (8 floats, 32B, coalesced).
__device__ float    g_ew[(size_t)NB * NV * NA];
// Monotonic per-batch arrival counters (replay-safe: act on (old&15)==15).
__device__ unsigned g_cnt[NB];

__global__ __launch_bounds__(256, 4) void garnet(
    const float* __restrict__ data, const int* __restrict__ num_vertex,
    const float* __restrict__ W_flr, const float* __restrict__ b_flr,
    const float* __restrict__ W_s,   const float* __restrict__ b_s,
    const float* __restrict__ W_out, const float* __restrict__ b_out,
    float* __restrict__ out)
{
    __shared__ float4 sWf4[NFEAT][4];
    __shared__ float4 sWs4[NFEAT][2];
    __shared__ float  sbf[NP];
    __shared__ float  sbs[NA];
    __shared__ float  sbo[NOUT];
    __shared__ float4 sStage[CH * 6];    // [0..3]=feat, [4..5]=ew; 24KB
    __shared__ float4 sRed[256];         // 4KB, separate from sStage
    __shared__ float  sFan[128];
    __shared__ __align__(16) float sM[128];
    __shared__ unsigned sLast;

    const int t     = threadIdx.x;
    const int lane  = t & 31;
    const int w     = t >> 5;
    const int b     = blockIdx.x / S1;
    const int split = blockIdx.x % S1;
    const int nv    = num_vertex[b];
    const int vbase = split * CH;
    const bool work = (vbase < nv);       // block-uniform
    const float4 z  = make_float4(0.f, 0.f, 0.f, 0.f);

    // =====================  Phase A  =====================
    if (work) {
        if (t < 64) {
            sWf4[t >> 2][t & 3] = ((const float4*)W_flr)[t];
        } else if (t < 96) {
            const int u = t - 64;
            sWs4[u >> 1][u & 1] = ((const float4*)W_s)[u];
        } else if (t < 112) {
            sbf[t - 96] = b_flr[t - 96];
        } else if (t < 120) {
            sbs[t - 112] = b_s[t - 112];
        }
        __syncthreads();

        const int v = vbase + t;
        if (v < nv) {
            const float4* dp = (const float4*)(data + ((size_t)(b * NV + v)) * NFEAT);
            const float4 x0 = dp[0], x1 = dp[1], x2 = dp[2], x3 = dp[3];
            float x[16];
            x[0]=x0.x;  x[1]=x0.y;  x[2]=x0.z;  x[3]=x0.w;
            x[4]=x1.x;  x[5]=x1.y;  x[6]=x1.z;  x[7]=x1.w;
            x[8]=x2.x;  x[9]=x2.y;  x[10]=x2.z; x[11]=x2.w;
            x[12]=x3.x; x[13]=x3.y; x[14]=x3.z; x[15]=x3.w;

            #pragma unroll
            for (int g = 0; g < 4; ++g) {
                float s0 = sbf[g*4+0], s1 = sbf[g*4+1];
                float s2 = sbf[g*4+2], s3 = sbf[g*4+3];
                #pragma unroll
                for (int f = 0; f < 16; ++f) {
                    const float4 wv = sWf4[f][g];
                    s0 += x[f]*wv.x; s1 += x[f]*wv.y;
                    s2 += x[f]*wv.z; s3 += x[f]*wv.w;
                }
                sStage[t*6 + g] = make_float4(s0, s1, s2, s3);
            }
            {
                float s0 = sbs[0], s1 = sbs[1], s2 = sbs[2], s3 = sbs[3];
                float u0 = sbs[4], u1 = sbs[5], u2 = sbs[6], u3 = sbs[7];
                #pragma unroll
                for (int f = 0; f < 16; ++f) {
                    const float4 w0 = sWs4[f][0];
                    const float4 w1 = sWs4[f][1];
                    s0 += x[f]*w0.x; s1 += x[f]*w0.y;
                    s2 += x[f]*w0.z; s3 += x[f]*w0.w;
                    u0 += x[f]*w1.x; u1 += x[f]*w1.y;
                    u2 += x[f]*w1.z; u3 += x[f]*w1.w;
                }
                const float4 e0 = make_float4(__expf(-s0*s0), __expf(-s1*s1),
                                              __expf(-s2*s2), __expf(-s3*s3));
                const float4 e1 = make_float4(__expf(-u0*u0), __expf(-u1*u1),
                                              __expf(-u2*u2), __expf(-u3*u3));
                sStage[t*6 + 4] = e0;
                sStage[t*6 + 5] = e1;
                float4* ewp = (float4*)(g_ew + ((size_t)(b * NV + v)) * NA);
                ewp[0] = e0; ewp[1] = e1;          // export for the tail
            }
        } else {
            #pragma unroll
            for (int g = 0; g < 6; ++g) sStage[t*6 + g] = z;
        }
        __syncwarp();

        // per-warp reduce over own 32 vertices (aa=lane>>2, pg=lane&3)
        const int aa = lane >> 2;
        const int pg = lane & 3;
        const float* sS = (const float*)sStage;
        float4 acc = z;
        if (vbase + w * 32 < nv) {
            const int r0 = w * 32;
            #pragma unroll 8
            for (int i = 0; i < 32; ++i) {
                const int vv = r0 + i;
                const float  ww = sS[vv*24 + 16 + aa];
                const float4 ff = sStage[vv*6 + pg];
                acc.x += ww * ff.x; acc.y += ww * ff.y;
                acc.z += ww * ff.z; acc.w += ww * ff.w;
            }
        }
        sRed[w * 32 + lane] = acc;
        __syncthreads();

        if (t < 32) {
            float4 s = sRed[t];
            #pragma unroll
            for (int sl = 1; sl < 8; ++sl) {
                const float4 r = sRed[sl * 32 + t];
                s.x += r.x; s.y += r.y; s.z += r.z; s.w += r.w;
            }
            ((float4*)g_part)[blockIdx.x * 32 + t] = s;
        }
    } else {
        if (t < 32)
            ((float4*)g_part)[blockIdx.x * 32 + t] = z;
    }

    // Make this block's g_ew + g_part writes visible gpu-wide, then arrive.
    __threadfence();
    __syncthreads();
    if (t == 0) {
        const unsigned old = atomicAdd(&g_cnt[b], 1u);
        sLast = ((old & (S1 - 1)) == (S1 - 1)) ? 1u : 0u;
    }
    __syncthreads();
    if (!sLast) return;                    // 15/16 blocks exit — no waiting

    // =====================  Tail (one block per batch)  =====================
    __threadfence();                       // acquire siblings' exports
    if (t < 32) {
        float4 s = z;
        #pragma unroll
        for (int sp = 0; sp < S1; ++sp) {
            const float4 r = ((const float4*)g_part)[(b * S1 + sp) * 32 + t];
            s.x += r.x; s.y += r.y; s.z += r.z; s.w += r.w;
        }
        const float inv = 1.0f / (float)NV;
        s.x *= inv; s.y *= inv; s.z *= inv; s.w *= inv;
        ((float4*)sFan)[t] = s;            // agg[a*16+p]
    } else if (t < 48) {
        sbo[t - 32] = b_out[t - 32];
    }
    __syncthreads();
    if (t < 128) {
        const int a = t >> 4, n = t & 15;
        float m = 0.f;
        #pragma unroll
        for (int p = 0; p < NP; ++p)
            m += sFan[a*NP + p] * W_out[(a*NP + p)*NOUT + n];
        sM[t] = m;
    }
    __syncthreads();

    // Output the whole batch: 16 chunks of 256 vertices.
    const float4 bo0 = make_float4(sbo[0],  sbo[1],  sbo[2],  sbo[3]);
    const float4 bo1 = make_float4(sbo[4],  sbo[5],  sbo[6],  sbo[7]);
    const float4 bo2 = make_float4(sbo[8],  sbo[9],  sbo[10], sbo[11]);
    const float4 bo3 = make_float4(sbo[12], sbo[13], sbo[14], sbo[15]);

    #pragma unroll 2
    for (int c = 0; c < S1; ++c) {
        const int v = c * CH + t;
        float4* op = (float4*)(out + ((size_t)(b * NV + v)) * NOUT);
        if (v < nv) {
            const float4* ep = (const float4*)(g_ew + ((size_t)(b * NV + v)) * NA);
            const float4 e0 = ep[0], e1 = ep[1];
            const float ew[8] = {e0.x, e0.y, e0.z, e0.w, e1.x, e1.y, e1.z, e1.w};
            float4 o0 = bo0, o1 = bo1, o2 = bo2, o3 = bo3;
            #pragma unroll
            for (int a = 0; a < NA; ++a) {
                const float wv = ew[a];
                const float4* mrow = (const float4*)(sM + a * NOUT);
                const float4 m0 = mrow[0], m1 = mrow[1], m2 = mrow[2], m3 = mrow[3];
                o0.x += wv*m0.x; o0.y += wv*m0.y; o0.z += wv*m0.z; o0.w += wv*m0.w;
                o1.x += wv*m1.x; o1.y += wv*m1.y; o1.z += wv*m1.z; o1.w += wv*m1.w;
                o2.x += wv*m2.x; o2.y += wv*m2.y; o2.z += wv*m2.z; o2.w += wv*m2.w;
                o3.x += wv*m3.x; o3.y += wv*m3.y; o3.z += wv*m3.z; o3.w += wv*m3.w;
            }
            op[0] = o0; op[1] = o1; op[2] = o2; op[3] = o3;
        } else {
            op[0] = z; op[1] = z; op[2] = z; op[3] = z;
        }
    }
}

extern "C" void kernel_launch(void* const* d_in, const int* in_sizes, int n_in,
                              void* d_out, int out_size) {
    const float* data       = (const float*)d_in[0];
    const int*   num_vertex = (const int*)  d_in[1];
    const float* W_flr      = (const float*)d_in[2];
    const float* b_flr      = (const float*)d_in[3];
    const float* W_s        = (const float*)d_in[4];
    const float* b_s        = (const float*)d_in[5];
    const float* W_out      = (const float*)d_in[6];
    const float* b_out      = (const float*)d_in[7];
    float* out = (float*)d_out;

    garnet<<<GRID1, 256>>>(data, num_vertex, W_flr, b_flr,
                           W_s, b_s, W_out, b_out, out);
}

// round 12
// speedup vs baseline: 2.5706x; 2.5706x over previous
#include <cuda_runtime.h>

#define NB    64
#define NV    4096
#define NFEAT 16
#define NA    8
#define NP    16
#define NOUT  16
#define S1    16                 // k1 blocks per batch
#define CH    256                // vertices per k1 block
#define GRID1 (NB * S1)          // 1024
#define S2    8                  // k2 blocks per batch
#define CHB   512                // vertices per k2 block (2/thread)
#define GRID2 (NB * S2)          // 512

// Per-(b,split) partials; slot owned exclusively -> no zeroing kernel.
__device__ float    g_part[GRID1 * 128];
// Per-batch M[a][n], produced by each batch's last-arriving k1 block.
__device__ float    g_M[NB * 128];
// Per-vertex edge weights exported by k1 (8 floats, 32B, coalesced).
__device__ float    g_ew[(size_t)NB * NV * NA];
// Monotonic per-batch arrival counters (replay-safe: act on (old&15)==15).
__device__ unsigned g_cnt[NB];

// ---------------------------------------------------------------------------
// k1 (R10 shape, measured 12.9us): per-warp staged aggregation + ew export +
//     per-batch fan-in -> g_M. Fences ONLY from the 32 partial-writer threads.
// ---------------------------------------------------------------------------
__global__ __launch_bounds__(256, 4) void k_aggregate(
    const float* __restrict__ data, const int* __restrict__ num_vertex,
    const float* __restrict__ W_flr, const float* __restrict__ b_flr,
    const float* __restrict__ W_s,   const float* __restrict__ b_s,
    const float* __restrict__ W_out)
{
    __shared__ float4 sWf4[NFEAT][4];
    __shared__ float4 sWs4[NFEAT][2];
    __shared__ float  sbf[NP];
    __shared__ float  sbs[NA];
    __shared__ float4 sStage[CH * 6];    // [0..3]=feat, [4..5]=ew; 24KB
    __shared__ float4 sRed[256];         // separate buffer, no aliasing
    __shared__ float  sFan[128];
    __shared__ unsigned sLast;

    const int t     = threadIdx.x;
    const int lane  = t & 31;
    const int w     = t >> 5;
    const int b     = blockIdx.x / S1;
    const int split = blockIdx.x % S1;
    const int nv    = num_vertex[b];
    const int vbase = split * CH;
    const bool work = (vbase < nv);       // block-uniform
    const float4 z  = make_float4(0.f, 0.f, 0.f, 0.f);

    if (work) {
        if (t < 64) {
            sWf4[t >> 2][t & 3] = ((const float4*)W_flr)[t];
        } else if (t < 96) {
            const int u = t - 64;
            sWs4[u >> 1][u & 1] = ((const float4*)W_s)[u];
        } else if (t < 112) {
            sbf[t - 96] = b_flr[t - 96];
        } else if (t < 120) {
            sbs[t - 112] = b_s[t - 112];
        }
        __syncthreads();

        const int v = vbase + t;
        if (v < nv) {
            const float4* dp = (const float4*)(data + ((size_t)(b * NV + v)) * NFEAT);
            const float4 x0 = dp[0], x1 = dp[1], x2 = dp[2], x3 = dp[3];
            float x[16];
            x[0]=x0.x;  x[1]=x0.y;  x[2]=x0.z;  x[3]=x0.w;
            x[4]=x1.x;  x[5]=x1.y;  x[6]=x1.z;  x[7]=x1.w;
            x[8]=x2.x;  x[9]=x2.y;  x[10]=x2.z; x[11]=x2.w;
            x[12]=x3.x; x[13]=x3.y; x[14]=x3.z; x[15]=x3.w;

            #pragma unroll
            for (int g = 0; g < 4; ++g) {
                float s0 = sbf[g*4+0], s1 = sbf[g*4+1];
                float s2 = sbf[g*4+2], s3 = sbf[g*4+3];
                #pragma unroll
                for (int f = 0; f < 16; ++f) {
                    const float4 wv = sWf4[f][g];
                    s0 += x[f]*wv.x; s1 += x[f]*wv.y;
                    s2 += x[f]*wv.z; s3 += x[f]*wv.w;
                }
                sStage[t*6 + g] = make_float4(s0, s1, s2, s3);
            }
            {
                float s0 = sbs[0], s1 = sbs[1], s2 = sbs[2], s3 = sbs[3];
                float u0 = sbs[4], u1 = sbs[5], u2 = sbs[6], u3 = sbs[7];
                #pragma unroll
                for (int f = 0; f < 16; ++f) {
                    const float4 w0 = sWs4[f][0];
                    const float4 w1 = sWs4[f][1];
                    s0 += x[f]*w0.x; s1 += x[f]*w0.y;
                    s2 += x[f]*w0.z; s3 += x[f]*w0.w;
                    u0 += x[f]*w1.x; u1 += x[f]*w1.y;
                    u2 += x[f]*w1.z; u3 += x[f]*w1.w;
                }
                const float4 e0 = make_float4(__expf(-s0*s0), __expf(-s1*s1),
                                              __expf(-s2*s2), __expf(-s3*s3));
                const float4 e1 = make_float4(__expf(-u0*u0), __expf(-u1*u1),
                                              __expf(-u2*u2), __expf(-u3*u3));
                sStage[t*6 + 4] = e0;
                sStage[t*6 + 5] = e1;
                float4* ewp = (float4*)(g_ew + ((size_t)(b * NV + v)) * NA);
                ewp[0] = e0; ewp[1] = e1;    // export for k2 (kernel-boundary vis.)
            }
        } else {
            #pragma unroll
            for (int g = 0; g < 6; ++g) sStage[t*6 + g] = z;
        }
        __syncwarp();

        // per-warp reduce over own 32 vertices (aa=lane>>2, pg=lane&3)
        const int aa = lane >> 2;
        const int pg = lane & 3;
        const float* sS = (const float*)sStage;
        float4 acc = z;
        if (vbase + w * 32 < nv) {           // warp-uniform dead-slice skip
            const int r0 = w * 32;
            #pragma unroll 8
            for (int i = 0; i < 32; ++i) {
                const int vv = r0 + i;
                const float  ww = sS[vv*24 + 16 + aa];
                const float4 ff = sStage[vv*6 + pg];
                acc.x += ww * ff.x; acc.y += ww * ff.y;
                acc.z += ww * ff.z; acc.w += ww * ff.w;
            }
        }
        sRed[w * 32 + lane] = acc;
        __syncthreads();

        if (t < 32) {
            float4 s = sRed[t];
            #pragma unroll
            for (int sl = 1; sl < 8; ++sl) {
                const float4 r = sRed[sl * 32 + t];
                s.x += r.x; s.y += r.y; s.z += r.z; s.w += r.w;
            }
            ((float4*)g_part)[blockIdx.x * 32 + t] = s;
            __threadfence();                 // release partial (32 threads only)
        }
    } else {
        if (t < 32) {
            ((float4*)g_part)[blockIdx.x * 32 + t] = z;
            __threadfence();
        }
    }
    __syncthreads();

    // ---- per-batch fan-in: last arrival reduces partials, computes M ----
    if (t == 0) {
        const unsigned old = atomicAdd(&g_cnt[b], 1u);
        sLast = ((old & (S1 - 1)) == (S1 - 1)) ? 1u : 0u;
    }
    __syncthreads();
    if (sLast) {
        __threadfence();                     // acquire siblings' partials
        if (t < 32) {
            float4 s = z;
            #pragma unroll
            for (int sp = 0; sp < S1; ++sp) {
                const float4 r = ((const float4*)g_part)[(b * S1 + sp) * 32 + t];
                s.x += r.x; s.y += r.y; s.z += r.z; s.w += r.w;
            }
            const float inv = 1.0f / (float)NV;
            s.x *= inv; s.y *= inv; s.z *= inv; s.w *= inv;
            ((float4*)sFan)[t] = s;          // agg[a*16+p]
        }
        __syncthreads();
        if (t < 128) {
            const int a = t >> 4, n = t & 15;
            float m = 0.f;
            #pragma unroll
            for (int p = 0; p < NP; ++p)
                m += sFan[a*NP + p] * W_out[(a*NP + p)*NOUT + n];
            g_M[b * 128 + t] = m;            // visible to k2 via launch edge
        }
    }
}

// ---------------------------------------------------------------------------
// k2 (R6 shape, measured 10.4us): out = mask*(sum_a ew[v,a]*M[b,a,:]+b_out).
//     g_M direct (no partial reduction), g_ew read, 2 vertices/thread.
// ---------------------------------------------------------------------------
__global__ __launch_bounds__(256, 4) void k_output(
    const int* __restrict__ num_vertex, const float* __restrict__ b_out,
    float* __restrict__ out)
{
    __shared__ __align__(16) float sM[128];
    __shared__ float sbo[NOUT];

    const int t  = threadIdx.x;
    const int b  = blockIdx.x / S2;
    const int vb = (blockIdx.x % S2) * CHB;
    const int nv = num_vertex[b];
    const float4 z = make_float4(0.f, 0.f, 0.f, 0.f);

    if (vb >= nv) {                          // fully masked: zero-fill 512 vertices
        #pragma unroll
        for (int s = 0; s < 2; ++s) {
            float4* op = (float4*)(out + ((size_t)(b * NV + vb + s*256 + t)) * NOUT);
            op[0] = z; op[1] = z; op[2] = z; op[3] = z;
        }
        return;
    }

    const int v0 = vb + t, v1 = vb + 256 + t;
    const bool val0 = (v0 < nv), val1 = (v1 < nv);

    // Hoist ew loads (L2-hot) to overlap the smem prologue.
    float4 e00 = z, e01 = z, e10 = z, e11 = z;
    if (val0) {
        const float4* ep = (const float4*)(g_ew + ((size_t)(b * NV + v0)) * NA);
        e00 = ep[0]; e01 = ep[1];
    }
    if (val1) {
        const float4* ep = (const float4*)(g_ew + ((size_t)(b * NV + v1)) * NA);
        e10 = ep[0]; e11 = ep[1];
    }

    if (t < 32) {
        ((float4*)sM)[t] = ((const float4*)g_M)[b * 32 + t];
    } else if (t < 48) {
        sbo[t - 32] = b_out[t - 32];
    }
    __syncthreads();

    const float ew0[8] = {e00.x, e00.y, e00.z, e00.w, e01.x, e01.y, e01.z, e01.w};
    const float ew1[8] = {e10.x, e10.y, e10.z, e10.w, e11.x, e11.y, e11.z, e11.w};

    float4 o0[4], o1[4];
    #pragma unroll
    for (int j = 0; j < 4; ++j) {
        o0[j] = make_float4(sbo[j*4], sbo[j*4+1], sbo[j*4+2], sbo[j*4+3]);
        o1[j] = o0[j];
    }
    #pragma unroll
    for (int a = 0; a < NA; ++a) {
        const float w0 = ew0[a], w1 = ew1[a];
        const float4* mrow = (const float4*)(sM + a * NOUT);
        #pragma unroll
        for (int j = 0; j < 4; ++j) {
            const float4 m = mrow[j];        // one LDS.128 serves both vertices
            o0[j].x += w0 * m.x; o0[j].y += w0 * m.y;
            o0[j].z += w0 * m.z; o0[j].w += w0 * m.w;
            o1[j].x += w1 * m.x; o1[j].y += w1 * m.y;
            o1[j].z += w1 * m.z; o1[j].w += w1 * m.w;
        }
    }

    float4* op0 = (float4*)(out + ((size_t)(b * NV + v0)) * NOUT);
    float4* op1 = (float4*)(out + ((size_t)(b * NV + v1)) * NOUT);
    if (val0) { op0[0]=o0[0]; op0[1]=o0[1]; op0[2]=o0[2]; op0[3]=o0[3]; }
    else      { op0[0]=z;     op0[1]=z;     op0[2]=z;     op0[3]=z;     }
    if (val1) { op1[0]=o1[0]; op1[1]=o1[1]; op1[2]=o1[2]; op1[3]=o1[3]; }
    else      { op1[0]=z;     op1[1]=z;     op1[2]=z;     op1[3]=z;     }
}

extern "C" void kernel_launch(void* const* d_in, const int* in_sizes, int n_in,
                              void* d_out, int out_size) {
    const float* data       = (const float*)d_in[0];
    const int*   num_vertex = (const int*)  d_in[1];
    const float* W_flr      = (const float*)d_in[2];
    const float* b_flr      = (const float*)d_in[3];
    const float* W_s        = (const float*)d_in[4];
    const float* b_s        = (const float*)d_in[5];
    const float* W_out      = (const float*)d_in[6];
    const float* b_out      = (const float*)d_in[7];
    float* out = (float*)d_out;

    k_aggregate<<<GRID1, 256>>>(data, num_vertex, W_flr, b_flr, W_s, b_s, W_out);
    k_output<<<GRID2, 256>>>(num_vertex, b_out, out);
}

// round 13
// speedup vs baseline: 3.8608x; 1.5019x over previous
#include <cuda_runtime.h>

#define NB    64
#define NV    4096
#define NFEAT 16
#define NA    8
#define NP    16
#define NOUT  16
#define S1    16                 // k1 blocks per batch
#define CH    256                // vertices per k1 block
#define GRID1 (NB * S1)          // 1024
#define S2    8                  // k2 blocks per batch
#define CHB   512                // vertices per k2 block (2/thread)
#define GRID2 (NB * S2)          // 512

// Per-(b,split) partials; slot owned exclusively -> no zeroing kernel.
__device__ float    g_part[GRID1 * 128];
// Per-batch M[a][n], produced by each batch's last-arriving k1 block.
__device__ float    g_M[NB * 128];
// Per-vertex edge weights exported by k1 (8 floats, 32B, coalesced).
__device__ float    g_ew[(size_t)NB * NV * NA];
// Monotonic per-batch arrival counters (replay-safe: act on (old&15)==15).
__device__ unsigned g_cnt[NB];

// ---------------------------------------------------------------------------
// k1: per-warp staged aggregation + ew export + per-batch fan-in -> g_M.
//     Data LDG hoisted above the weight-staging barrier (DRAM/smem overlap).
// ---------------------------------------------------------------------------
__global__ __launch_bounds__(256, 4) void k_aggregate(
    const float* __restrict__ data, const int* __restrict__ num_vertex,
    const float* __restrict__ W_flr, const float* __restrict__ b_flr,
    const float* __restrict__ W_s,   const float* __restrict__ b_s,
    const float* __restrict__ W_out)
{
    __shared__ float4 sWf4[NFEAT][4];
    __shared__ float4 sWs4[NFEAT][2];
    __shared__ float  sbf[NP];
    __shared__ float  sbs[NA];
    __shared__ float4 sStage[CH * 6];    // [0..3]=feat, [4..5]=ew; 24KB
    __shared__ float4 sRed[256];         // separate buffer, no aliasing
    __shared__ float  sFan[128];
    __shared__ unsigned sLast;

    const int t     = threadIdx.x;
    const int lane  = t & 31;
    const int w     = t >> 5;
    const int b     = blockIdx.x / S1;
    const int split = blockIdx.x % S1;
    const int nv    = num_vertex[b];
    const int vbase = split * CH;
    const bool work = (vbase < nv);       // block-uniform
    const float4 z  = make_float4(0.f, 0.f, 0.f, 0.f);

    if (work) {
        // ---- hoist vertex data load: overlaps the weight smem fill below ----
        const int v = vbase + t;
        const bool valid = (v < nv);
        float4 x0 = z, x1 = z, x2 = z, x3 = z;
        if (valid) {
            const float4* dp = (const float4*)(data + ((size_t)(b * NV + v)) * NFEAT);
            x0 = dp[0]; x1 = dp[1]; x2 = dp[2]; x3 = dp[3];
        }

        if (t < 64) {
            sWf4[t >> 2][t & 3] = ((const float4*)W_flr)[t];
        } else if (t < 96) {
            const int u = t - 64;
            sWs4[u >> 1][u & 1] = ((const float4*)W_s)[u];
        } else if (t < 112) {
            sbf[t - 96] = b_flr[t - 96];
        } else if (t < 120) {
            sbs[t - 112] = b_s[t - 112];
        }
        __syncthreads();

        if (valid) {
            float x[16];
            x[0]=x0.x;  x[1]=x0.y;  x[2]=x0.z;  x[3]=x0.w;
            x[4]=x1.x;  x[5]=x1.y;  x[6]=x1.z;  x[7]=x1.w;
            x[8]=x2.x;  x[9]=x2.y;  x[10]=x2.z; x[11]=x2.w;
            x[12]=x3.x; x[13]=x3.y; x[14]=x3.z; x[15]=x3.w;

            #pragma unroll
            for (int g = 0; g < 4; ++g) {
                float s0 = sbf[g*4+0], s1 = sbf[g*4+1];
                float s2 = sbf[g*4+2], s3 = sbf[g*4+3];
                #pragma unroll
                for (int f = 0; f < 16; ++f) {
                    const float4 wv = sWf4[f][g];
                    s0 += x[f]*wv.x; s1 += x[f]*wv.y;
                    s2 += x[f]*wv.z; s3 += x[f]*wv.w;
                }
                sStage[t*6 + g] = make_float4(s0, s1, s2, s3);
            }
            {
                float s0 = sbs[0], s1 = sbs[1], s2 = sbs[2], s3 = sbs[3];
                float u0 = sbs[4], u1 = sbs[5], u2 = sbs[6], u3 = sbs[7];
                #pragma unroll
                for (int f = 0; f < 16; ++f) {
                    const float4 w0 = sWs4[f][0];
                    const float4 w1 = sWs4[f][1];
                    s0 += x[f]*w0.x; s1 += x[f]*w0.y;
                    s2 += x[f]*w0.z; s3 += x[f]*w0.w;
                    u0 += x[f]*w1.x; u1 += x[f]*w1.y;
                    u2 += x[f]*w1.z; u3 += x[f]*w1.w;
                }
                const float4 e0 = make_float4(__expf(-s0*s0), __expf(-s1*s1),
                                              __expf(-s2*s2), __expf(-s3*s3));
                const float4 e1 = make_float4(__expf(-u0*u0), __expf(-u1*u1),
                                              __expf(-u2*u2), __expf(-u3*u3));
                sStage[t*6 + 4] = e0;
                sStage[t*6 + 5] = e1;
                float4* ewp = (float4*)(g_ew + ((size_t)(b * NV + v)) * NA);
                ewp[0] = e0; ewp[1] = e1;    // export for k2 (launch-edge vis.)
            }
        } else {
            #pragma unroll
            for (int g = 0; g < 6; ++g) sStage[t*6 + g] = z;
        }
        __syncwarp();

        // per-warp reduce over own 32 vertices (aa=lane>>2, pg=lane&3)
        const int aa = lane >> 2;
        const int pg = lane & 3;
        const float* sS = (const float*)sStage;
        float4 acc = z;
        if (vbase + w * 32 < nv) {           // warp-uniform dead-slice skip
            const int r0 = w * 32;
            #pragma unroll 8
            for (int i = 0; i < 32; ++i) {
                const int vv = r0 + i;
                const float  ww = sS[vv*24 + 16 + aa];
                const float4 ff = sStage[vv*6 + pg];
                acc.x += ww * ff.x; acc.y += ww * ff.y;
                acc.z += ww * ff.z; acc.w += ww * ff.w;
            }
        }
        sRed[w * 32 + lane] = acc;
        __syncthreads();

        if (t < 32) {
            float4 s = sRed[t];
            #pragma unroll
            for (int sl = 1; sl < 8; ++sl) {
                const float4 r = sRed[sl * 32 + t];
                s.x += r.x; s.y += r.y; s.z += r.z; s.w += r.w;
            }
            ((float4*)g_part)[blockIdx.x * 32 + t] = s;
            __threadfence();                 // release partial (32 threads only)
        }
    } else {
        if (t < 32) {
            ((float4*)g_part)[blockIdx.x * 32 + t] = z;
            __threadfence();
        }
    }
    __syncthreads();

    // ---- per-batch fan-in: last arrival reduces partials, computes M ----
    if (t == 0) {
        const unsigned old = atomicAdd(&g_cnt[b], 1u);
        sLast = ((old & (S1 - 1)) == (S1 - 1)) ? 1u : 0u;
    }
    __syncthreads();
    if (sLast) {
        __threadfence();                     // acquire siblings' partials
        if (t < 32) {
            float4 s = z;
            #pragma unroll
            for (int sp = 0; sp < S1; ++sp) {
                const float4 r = ((const float4*)g_part)[(b * S1 + sp) * 32 + t];
                s.x += r.x; s.y += r.y; s.z += r.z; s.w += r.w;
            }
            const float inv = 1.0f / (float)NV;
            s.x *= inv; s.y *= inv; s.z *= inv; s.w *= inv;
            ((float4*)sFan)[t] = s;          // agg[a*16+p]
        }
        __syncthreads();
        if (t < 128) {
            const int a = t >> 4, n = t & 15;
            float m = 0.f;
            #pragma unroll
            for (int p = 0; p < NP; ++p)
                m += sFan[a*NP + p] * W_out[(a*NP + p)*NOUT + n];
            g_M[b * 128 + t] = m;            // visible to k2 via launch edge
        }
    }
}

// ---------------------------------------------------------------------------
// k2: out = mask*(sum_a ew[v,a]*M[b,a,:]+b_out). g_M direct, g_ew read,
//     2 vertices/thread, hoisted loads.
// ---------------------------------------------------------------------------
__global__ __launch_bounds__(256, 4) void k_output(
    const int* __restrict__ num_vertex, const float* __restrict__ b_out,
    float* __restrict__ out)
{
    __shared__ __align__(16) float sM[128];
    __shared__ float sbo[NOUT];

    const int t  = threadIdx.x;
    const int b  = blockIdx.x / S2;
    const int vb = (blockIdx.x % S2) * CHB;
    const int nv = num_vertex[b];
    const float4 z = make_float4(0.f, 0.f, 0.f, 0.f);

    const int v0 = vb + t, v1 = vb + 256 + t;
    float4* op0 = (float4*)(out + ((size_t)(b * NV + v0)) * NOUT);
    float4* op1 = (float4*)(out + ((size_t)(b * NV + v1)) * NOUT);

    if (vb >= nv) {                          // fully masked: zero-fill
        op0[0] = z; op0[1] = z; op0[2] = z; op0[3] = z;
        op1[0] = z; op1[1] = z; op1[2] = z; op1[3] = z;
        return;
    }

    const bool val0 = (v0 < nv), val1 = (v1 < nv);

    // Hoist ew loads (L2-hot) to overlap the smem prologue.
    float4 e00 = z, e01 = z, e10 = z, e11 = z;
    if (val0) {
        const float4* ep = (const float4*)(g_ew + ((size_t)(b * NV + v0)) * NA);
        e00 = ep[0]; e01 = ep[1];
    }
    if (val1) {
        const float4* ep = (const float4*)(g_ew + ((size_t)(b * NV + v1)) * NA);
        e10 = ep[0]; e11 = ep[1];
    }

    if (t < 32) {
        ((float4*)sM)[t] = ((const float4*)g_M)[b * 32 + t];
    } else if (t < 48) {
        sbo[t - 32] = b_out[t - 32];
    }
    __syncthreads();

    const float ew0[8] = {e00.x, e00.y, e00.z, e00.w, e01.x, e01.y, e01.z, e01.w};
    const float ew1[8] = {e10.x, e10.y, e10.z, e10.w, e11.x, e11.y, e11.z, e11.w};

    float4 o0[4], o1[4];
    #pragma unroll
    for (int j = 0; j < 4; ++j) {
        o0[j] = make_float4(sbo[j*4], sbo[j*4+1], sbo[j*4+2], sbo[j*4+3]);
        o1[j] = o0[j];
    }
    #pragma unroll
    for (int a = 0; a < NA; ++a) {
        const float w0 = ew0[a], w1 = ew1[a];
        const float4* mrow = (const float4*)(sM + a * NOUT);
        #pragma unroll
        for (int j = 0; j < 4; ++j) {
            const float4 m = mrow[j];        // one LDS.128 serves both vertices
            o0[j].x += w0 * m.x; o0[j].y += w0 * m.y;
            o0[j].z += w0 * m.z; o0[j].w += w0 * m.w;
            o1[j].x += w1 * m.x; o1[j].y += w1 * m.y;
            o1[j].z += w1 * m.z; o1[j].w += w1 * m.w;
        }
    }

    if (val0) { op0[0]=o0[0]; op0[1]=o0[1]; op0[2]=o0[2]; op0[3]=o0[3]; }
    else      { op0[0]=z;     op0[1]=z;     op0[2]=z;     op0[3]=z;     }
    if (val1) { op1[0]=o1[0]; op1[1]=o1[1]; op1[2]=o1[2]; op1[3]=o1[3]; }
    else      { op1[0]=z;     op1[1]=z;     op1[2]=z;     op1[3]=z;     }
}

extern "C" void kernel_launch(void* const* d_in, const int* in_sizes, int n_in,
                              void* d_out, int out_size) {
    const float* data       = (const float*)d_in[0];
    const int*   num_vertex = (const int*)  d_in[1];
    const float* W_flr      = (const float*)d_in[2];
    const float* b_flr      = (const float*)d_in[3];
    const float* W_s        = (const float*)d_in[4];
    const float* b_s        = (const float*)d_in[5];
    const float* W_out      = (const float*)d_in[6];
    const float* b_out      = (const float*)d_in[7];
    float* out = (float*)d_out;

    k_aggregate<<<GRID1, 256>>>(data, num_vertex, W_flr, b_flr, W_s, b_s, W_out);
    k_output<<<GRID2, 256>>>(num_vertex, b_out, out);
}

// round 14
// speedup vs baseline: 4.1986x; 1.0875x over previous
#include <cuda_runtime.h>

#define NB    64
#define NV    4096
#define NFEAT 16
#define NA    8
#define NP    16
#define NOUT  16
#define S1    16                 // k1 blocks per batch
#define CH    256                // vertices per k1 block
#define GRID1 (NB * S1)          // 1024
#define S2    8                  // k2 blocks per batch
#define CHB   512                // vertices per k2 block (2/thread)
#define GRID2 (NB * S2)          // 512

// Per-(b,split) partials; slot owned exclusively -> no zeroing kernel.
__device__ float    g_part[GRID1 * 128];
// Per-batch M[a][n], produced by each batch's last-arriving k1 block.
__device__ float    g_M[NB * 128];
// Per-vertex edge weights exported by k1 (8 floats, 32B, coalesced).
__device__ float    g_ew[(size_t)NB * NV * NA];
// Monotonic per-batch arrival counters (replay-safe: act on (old&15)==15).
__device__ unsigned g_cnt[NB];

// ---------------------------------------------------------------------------
// k1: per-warp staged aggregation + ew export + per-batch fan-in -> g_M.
//     Triggers programmatic launch of k2 once the heavy phase is done.
// ---------------------------------------------------------------------------
__global__ __launch_bounds__(256, 4) void k_aggregate(
    const float* __restrict__ data, const int* __restrict__ num_vertex,
    const float* __restrict__ W_flr, const float* __restrict__ b_flr,
    const float* __restrict__ W_s,   const float* __restrict__ b_s,
    const float* __restrict__ W_out)
{
    __shared__ float4 sWf4[NFEAT][4];
    __shared__ float4 sWs4[NFEAT][2];
    __shared__ float  sbf[NP];
    __shared__ float  sbs[NA];
    __shared__ float4 sStage[CH * 6];    // [0..3]=feat, [4..5]=ew; 24KB
    __shared__ float4 sRed[256];
    __shared__ float  sFan[128];
    __shared__ unsigned sLast;

    const int t     = threadIdx.x;
    const int lane  = t & 31;
    const int w     = t >> 5;
    const int b     = blockIdx.x / S1;
    const int split = blockIdx.x % S1;
    const int nv    = num_vertex[b];
    const int vbase = split * CH;
    const bool work = (vbase < nv);       // block-uniform
    const float4 z  = make_float4(0.f, 0.f, 0.f, 0.f);

    if (work) {
        // hoist vertex data load: overlaps the weight smem fill below
        const int v = vbase + t;
        const bool valid = (v < nv);
        float4 x0 = z, x1 = z, x2 = z, x3 = z;
        if (valid) {
            const float4* dp = (const float4*)(data + ((size_t)(b * NV + v)) * NFEAT);
            x0 = dp[0]; x1 = dp[1]; x2 = dp[2]; x3 = dp[3];
        }

        if (t < 64) {
            sWf4[t >> 2][t & 3] = ((const float4*)W_flr)[t];
        } else if (t < 96) {
            const int u = t - 64;
            sWs4[u >> 1][u & 1] = ((const float4*)W_s)[u];
        } else if (t < 112) {
            sbf[t - 96] = b_flr[t - 96];
        } else if (t < 120) {
            sbs[t - 112] = b_s[t - 112];
        }
        __syncthreads();

        if (valid) {
            float x[16];
            x[0]=x0.x;  x[1]=x0.y;  x[2]=x0.z;  x[3]=x0.w;
            x[4]=x1.x;  x[5]=x1.y;  x[6]=x1.z;  x[7]=x1.w;
            x[8]=x2.x;  x[9]=x2.y;  x[10]=x2.z; x[11]=x2.w;
            x[12]=x3.x; x[13]=x3.y; x[14]=x3.z; x[15]=x3.w;

            #pragma unroll
            for (int g = 0; g < 4; ++g) {
                float s0 = sbf[g*4+0], s1 = sbf[g*4+1];
                float s2 = sbf[g*4+2], s3 = sbf[g*4+3];
                #pragma unroll
                for (int f = 0; f < 16; ++f) {
                    const float4 wv = sWf4[f][g];
                    s0 += x[f]*wv.x; s1 += x[f]*wv.y;
                    s2 += x[f]*wv.z; s3 += x[f]*wv.w;
                }
                sStage[t*6 + g] = make_float4(s0, s1, s2, s3);
            }
            {
                float s0 = sbs[0], s1 = sbs[1], s2 = sbs[2], s3 = sbs[3];
                float u0 = sbs[4], u1 = sbs[5], u2 = sbs[6], u3 = sbs[7];
                #pragma unroll
                for (int f = 0; f < 16; ++f) {
                    const float4 w0 = sWs4[f][0];
                    const float4 w1 = sWs4[f][1];
                    s0 += x[f]*w0.x; s1 += x[f]*w0.y;
                    s2 += x[f]*w0.z; s3 += x[f]*w0.w;
                    u0 += x[f]*w1.x; u1 += x[f]*w1.y;
                    u2 += x[f]*w1.z; u3 += x[f]*w1.w;
                }
                const float4 e0 = make_float4(__expf(-s0*s0), __expf(-s1*s1),
                                              __expf(-s2*s2), __expf(-s3*s3));
                const float4 e1 = make_float4(__expf(-u0*u0), __expf(-u1*u1),
                                              __expf(-u2*u2), __expf(-u3*u3));
                sStage[t*6 + 4] = e0;
                sStage[t*6 + 5] = e1;
                float4* ewp = (float4*)(g_ew + ((size_t)(b * NV + v)) * NA);
                ewp[0] = e0; ewp[1] = e1;    // export for k2
            }
        } else {
            #pragma unroll
            for (int g = 0; g < 6; ++g) sStage[t*6 + g] = z;
        }
        __syncwarp();

        // per-warp reduce over own 32 vertices (aa=lane>>2, pg=lane&3)
        const int aa = lane >> 2;
        const int pg = lane & 3;
        const float* sS = (const float*)sStage;
        float4 acc = z;
        if (vbase + w * 32 < nv) {
            const int r0 = w * 32;
            #pragma unroll 8
            for (int i = 0; i < 32; ++i) {
                const int vv = r0 + i;
                const float  ww = sS[vv*24 + 16 + aa];
                const float4 ff = sStage[vv*6 + pg];
                acc.x += ww * ff.x; acc.y += ww * ff.y;
                acc.z += ww * ff.z; acc.w += ww * ff.w;
            }
        }
        sRed[w * 32 + lane] = acc;
        __syncthreads();

        if (t < 32) {
            float4 s = sRed[t];
            #pragma unroll
            for (int sl = 1; sl < 8; ++sl) {
                const float4 r = sRed[sl * 32 + t];
                s.x += r.x; s.y += r.y; s.z += r.z; s.w += r.w;
            }
            ((float4*)g_part)[blockIdx.x * 32 + t] = s;
            __threadfence();                 // release partial (32 threads only)
        }
    } else {
        if (t < 32) {
            ((float4*)g_part)[blockIdx.x * 32 + t] = z;
            __threadfence();
        }
    }
    __syncthreads();

    // Heavy phase done -> allow k2's blocks to begin scheduling now.
    // (k2 still can't READ our outputs until cudaGridDependencySynchronize
    //  returns, which requires this whole grid to complete.)
    cudaTriggerProgrammaticLaunchCompletion();

    // ---- per-batch fan-in: last arrival reduces partials, computes M ----
    if (t == 0) {
        const unsigned old = atomicAdd(&g_cnt[b], 1u);
        sLast = ((old & (S1 - 1)) == (S1 - 1)) ? 1u : 0u;
    }
    __syncthreads();
    if (sLast) {
        __threadfence();                     // acquire siblings' partials
        if (t < 32) {
            float4 s = z;
            #pragma unroll
            for (int sp = 0; sp < S1; ++sp) {
                const float4 r = ((const float4*)g_part)[(b * S1 + sp) * 32 + t];
                s.x += r.x; s.y += r.y; s.z += r.z; s.w += r.w;
            }
            const float inv = 1.0f / (float)NV;
            s.x *= inv; s.y *= inv; s.z *= inv; s.w *= inv;
            ((float4*)sFan)[t] = s;          // agg[a*16+p]
        }
        __syncthreads();
        if (t < 128) {
            const int a = t >> 4, n = t & 15;
            float m = 0.f;
            #pragma unroll
            for (int p = 0; p < NP; ++p)
                m += sFan[a*NP + p] * W_out[(a*NP + p)*NOUT + n];
            g_M[b * 128 + t] = m;
        }
    }
}

// ---------------------------------------------------------------------------
// k2: PDL secondary. Pre-sync: only k1-independent setup. Post-sync: g_M/g_ew.
// ---------------------------------------------------------------------------
__global__ __launch_bounds__(256, 4) void k_output(
    const int* __restrict__ num_vertex, const float* __restrict__ b_out,
    float* __restrict__ out)
{
    __shared__ __align__(16) float sM[128];
    __shared__ float sbo[NOUT];

    const int t  = threadIdx.x;
    const int b  = blockIdx.x / S2;
    const int vb = (blockIdx.x % S2) * CHB;
    const int nv = num_vertex[b];           // input tensor: safe pre-sync
    const float4 z = make_float4(0.f, 0.f, 0.f, 0.f);

    const int v0 = vb + t, v1 = vb + 256 + t;
    float4* op0 = (float4*)(out + ((size_t)(b * NV + v0)) * NOUT);
    float4* op1 = (float4*)(out + ((size_t)(b * NV + v1)) * NOUT);

    if (vb >= nv) {                          // zero-fill path needs no k1 data,
        cudaGridDependencySynchronize();     // but out must not race with... out
        op0[0] = z; op0[1] = z; op0[2] = z; op0[3] = z;   // is not written by k1;
        op1[0] = z; op1[1] = z; op1[2] = z; op1[3] = z;   // sync kept for safety
        return;
    }

    if (t < 48 && t >= 32) sbo[t - 32] = b_out[t - 32];   // input: safe pre-sync
    const bool val0 = (v0 < nv), val1 = (v1 < nv);

    // ---- wait for k1's writes (g_M, g_ew) to be visible ----
    cudaGridDependencySynchronize();

    float4 e00 = z, e01 = z, e10 = z, e11 = z;
    if (val0) {
        const float4* ep = (const float4*)(g_ew + ((size_t)(b * NV + v0)) * NA);
        e00 = ep[0]; e01 = ep[1];
    }
    if (val1) {
        const float4* ep = (const float4*)(g_ew + ((size_t)(b * NV + v1)) * NA);
        e10 = ep[0]; e11 = ep[1];
    }
    if (t < 32) ((float4*)sM)[t] = ((const float4*)g_M)[b * 32 + t];
    __syncthreads();

    const float ew0[8] = {e00.x, e00.y, e00.z, e00.w, e01.x, e01.y, e01.z, e01.w};
    const float ew1[8] = {e10.x, e10.y, e10.z, e10.w, e11.x, e11.y, e11.z, e11.w};

    float4 o0[4], o1[4];
    #pragma unroll
    for (int j = 0; j < 4; ++j) {
        o0[j] = make_float4(sbo[j*4], sbo[j*4+1], sbo[j*4+2], sbo[j*4+3]);
        o1[j] = o0[j];
    }
    #pragma unroll
    for (int a = 0; a < NA; ++a) {
        const float w0 = ew0[a], w1 = ew1[a];
        const float4* mrow = (const float4*)(sM + a * NOUT);
        #pragma unroll
        for (int j = 0; j < 4; ++j) {
            const float4 m = mrow[j];        // one LDS.128 serves both vertices
            o0[j].x += w0 * m.x; o0[j].y += w0 * m.y;
            o0[j].z += w0 * m.z; o0[j].w += w0 * m.w;
            o1[j].x += w1 * m.x; o1[j].y += w1 * m.y;
            o1[j].z += w1 * m.z; o1[j].w += w1 * m.w;
        }
    }

    if (val0) { op0[0]=o0[0]; op0[1]=o0[1]; op0[2]=o0[2]; op0[3]=o0[3]; }
    else      { op0[0]=z;     op0[1]=z;     op0[2]=z;     op0[3]=z;     }
    if (val1) { op1[0]=o1[0]; op1[1]=o1[1]; op1[2]=o1[2]; op1[3]=o1[3]; }
    else      { op1[0]=z;     op1[1]=z;     op1[2]=z;     op1[3]=z;     }
}

extern "C" void kernel_launch(void* const* d_in, const int* in_sizes, int n_in,
                              void* d_out, int out_size) {
    const float* data       = (const float*)d_in[0];
    const int*   num_vertex = (const int*)  d_in[1];
    const float* W_flr      = (const float*)d_in[2];
    const float* b_flr      = (const float*)d_in[3];
    const float* W_s        = (const float*)d_in[4];
    const float* b_s        = (const float*)d_in[5];
    const float* W_out      = (const float*)d_in[6];
    const float* b_out      = (const float*)d_in[7];
    float* out = (float*)d_out;

    k_aggregate<<<GRID1, 256>>>(data, num_vertex, W_flr, b_flr, W_s, b_s, W_out);

    // PDL secondary: may begin scheduling once k1 triggers; memory dependency
    // enforced inside k2 via cudaGridDependencySynchronize().
    cudaLaunchConfig_t cfg = {};
    cfg.gridDim  = dim3(GRID2, 1, 1);
    cfg.blockDim = dim3(256, 1, 1);
    cudaLaunchAttribute attrs[1];
    attrs[0].id = cudaLaunchAttributeProgrammaticStreamSerialization;
    attrs[0].val.programmaticStreamSerializationAllowed = 1;
    cfg.attrs = attrs;
    cfg.numAttrs = 1;
    cudaLaunchKernelEx(&cfg, k_output, num_vertex, b_out, out);
}

// round 15
// speedup vs baseline: 4.2638x; 1.0155x over previous
#include <cuda_runtime.h>

#define NB    64
#define NV    4096
#define NFEAT 16
#define NA    8
#define NP    16
#define NOUT  16
#define S1    16                 // k1 blocks per batch
#define CH    256                // vertices per k1 block
#define GRID1 (NB * S1)          // 1024
#define S2    8                  // k2 blocks per batch
#define CHB   512                // vertices per k2 block (2/thread)
#define GRID2 (NB * S2)          // 512
#define PSTR  144                // floats per g_part slot: Y[128] + S[8] + pad

// Per-(b,split) partials: Y[a][p-quad] (128 floats) + S[a] (8 floats).
__device__ float    g_part[GRID1 * PSTR];
// Per-batch M[a][n], produced by each batch's last-arriving k1 block.
__device__ float    g_M[NB * 128];
// Per-vertex edge weights exported by k1 (8 floats, 32B, coalesced).
__device__ float    g_ew[(size_t)NB * NV * NA];
// Monotonic per-batch arrival counters (replay-safe: act on (old&15)==15).
__device__ unsigned g_cnt[NB];

// ---------------------------------------------------------------------------
// k1: x-space aggregation. Per vertex: ONLY the distance matvec + exp.
//     Reduce Y = ew^T X and S = sum(ew); fan-in converts via W_flr/b_flr.
// ---------------------------------------------------------------------------
__global__ __launch_bounds__(256, 4) void k_aggregate(
    const float* __restrict__ data, const int* __restrict__ num_vertex,
    const float* __restrict__ W_flr, const float* __restrict__ b_flr,
    const float* __restrict__ W_s,   const float* __restrict__ b_s,
    const float* __restrict__ W_out)
{
    __shared__ float4 sWs4[NFEAT][2];
    __shared__ float  sbs[NA];
    __shared__ float4 sStage[CH * 6];    // [0..3]=x, [4..5]=ew; 24KB
    __shared__ float4 sRed[256];         // Y cross-slice
    __shared__ float  sRedS[256];        // S cross-slice
    __shared__ float  sFanY[128];        // summed Y[a][f]
    __shared__ float  sFanS[NA];
    __shared__ float  sAgg[128];
    __shared__ unsigned sLast;

    const int t     = threadIdx.x;
    const int lane  = t & 31;
    const int w     = t >> 5;
    const int b     = blockIdx.x / S1;
    const int split = blockIdx.x % S1;
    const int nv    = num_vertex[b];
    const int vbase = split * CH;
    const bool work = (vbase < nv);       // block-uniform
    const float4 z  = make_float4(0.f, 0.f, 0.f, 0.f);

    if (work) {
        // hoist vertex data load: overlaps the weight smem fill below
        const int v = vbase + t;
        const bool valid = (v < nv);
        float4 x0 = z, x1 = z, x2 = z, x3 = z;
        if (valid) {
            const float4* dp = (const float4*)(data + ((size_t)(b * NV + v)) * NFEAT);
            x0 = dp[0]; x1 = dp[1]; x2 = dp[2]; x3 = dp[3];
        }

        if (t < 32) {
            sWs4[t >> 1][t & 1] = ((const float4*)W_s)[t];
        } else if (t < 40) {
            sbs[t - 32] = b_s[t - 32];
        }
        __syncthreads();

        if (valid) {
            float x[16];
            x[0]=x0.x;  x[1]=x0.y;  x[2]=x0.z;  x[3]=x0.w;
            x[4]=x1.x;  x[5]=x1.y;  x[6]=x1.z;  x[7]=x1.w;
            x[8]=x2.x;  x[9]=x2.y;  x[10]=x2.z; x[11]=x2.w;
            x[12]=x3.x; x[13]=x3.y; x[14]=x3.z; x[15]=x3.w;

            // stage raw x (no feature matvec needed!)
            sStage[t*6 + 0] = x0; sStage[t*6 + 1] = x1;
            sStage[t*6 + 2] = x2; sStage[t*6 + 3] = x3;

            float s0 = sbs[0], s1 = sbs[1], s2 = sbs[2], s3 = sbs[3];
            float u0 = sbs[4], u1 = sbs[5], u2 = sbs[6], u3 = sbs[7];
            #pragma unroll
            for (int f = 0; f < 16; ++f) {
                const float4 w0 = sWs4[f][0];
                const float4 w1 = sWs4[f][1];
                s0 += x[f]*w0.x; s1 += x[f]*w0.y;
                s2 += x[f]*w0.z; s3 += x[f]*w0.w;
                u0 += x[f]*w1.x; u1 += x[f]*w1.y;
                u2 += x[f]*w1.z; u3 += x[f]*w1.w;
            }
            const float4 e0 = make_float4(__expf(-s0*s0), __expf(-s1*s1),
                                          __expf(-s2*s2), __expf(-s3*s3));
            const float4 e1 = make_float4(__expf(-u0*u0), __expf(-u1*u1),
                                          __expf(-u2*u2), __expf(-u3*u3));
            sStage[t*6 + 4] = e0;
            sStage[t*6 + 5] = e1;
            float4* ewp = (float4*)(g_ew + ((size_t)(b * NV + v)) * NA);
            ewp[0] = e0; ewp[1] = e1;        // export for k2
        } else {
            #pragma unroll
            for (int g = 0; g < 6; ++g) sStage[t*6 + g] = z;
        }
        __syncwarp();

        // per-warp reduce over own 32 vertices: Y[aa][pg*4..] and S[aa]
        const int aa = lane >> 2;
        const int pg = lane & 3;
        const float* sS = (const float*)sStage;
        float4 acc = z;
        float ssum = 0.f;
        if (vbase + w * 32 < nv) {           // warp-uniform dead-slice skip
            const int r0 = w * 32;
            #pragma unroll 8
            for (int i = 0; i < 32; ++i) {
                const int vv = r0 + i;
                const float  ww = sS[vv*24 + 16 + aa];
                const float4 ff = sStage[vv*6 + pg];
                acc.x += ww * ff.x; acc.y += ww * ff.y;
                acc.z += ww * ff.z; acc.w += ww * ff.w;
                ssum += ww;                  // only pg==0 lanes' value is used
            }
        }
        sRed[w * 32 + lane]  = acc;
        sRedS[w * 32 + lane] = ssum;
        __syncthreads();

        if (t < 32) {
            float4 s = sRed[t];
            #pragma unroll
            for (int sl = 1; sl < 8; ++sl) {
                const float4 r = sRed[sl * 32 + t];
                s.x += r.x; s.y += r.y; s.z += r.z; s.w += r.w;
            }
            ((float4*)g_part)[blockIdx.x * (PSTR/4) + t] = s;
            if ((t & 3) == 0) {              // pg==0 owners carry S[aa]
                float sv = sRedS[t];
                #pragma unroll
                for (int sl = 1; sl < 8; ++sl) sv += sRedS[sl * 32 + t];
                g_part[blockIdx.x * PSTR + 128 + (t >> 2)] = sv;
            }
            __threadfence();                 // release partial (32 threads only)
        }
    } else {
        if (t < 32) {
            ((float4*)g_part)[blockIdx.x * (PSTR/4) + t] = z;
            if ((t & 3) == 0)
                g_part[blockIdx.x * PSTR + 128 + (t >> 2)] = 0.f;
            __threadfence();
        }
    }
    __syncthreads();

    // Heavy phase done -> let k2's blocks begin scheduling (PDL).
    cudaTriggerProgrammaticLaunchCompletion();

    // ---- per-batch fan-in: Y,S -> agg (via W_flr,b_flr) -> M (via W_out) ----
    if (t == 0) {
        const unsigned old = atomicAdd(&g_cnt[b], 1u);
        sLast = ((old & (S1 - 1)) == (S1 - 1)) ? 1u : 0u;
    }
    __syncthreads();
    if (sLast) {
        __threadfence();                     // acquire siblings' partials
        if (t < 32) {
            float4 s = z;
            #pragma unroll
            for (int sp = 0; sp < S1; ++sp) {
                const float4 r = ((const float4*)g_part)[(b * S1 + sp) * (PSTR/4) + t];
                s.x += r.x; s.y += r.y; s.z += r.z; s.w += r.w;
            }
            ((float4*)sFanY)[t] = s;         // Y[a][16] raw sums
        } else if (t < 40) {
            const int a = t - 32;
            float sv = 0.f;
            #pragma unroll
            for (int sp = 0; sp < S1; ++sp)
                sv += g_part[(b * S1 + sp) * PSTR + 128 + a];
            sFanS[a] = sv;
        }
        __syncthreads();
        if (t < 128) {                        // agg[a,p] = (Y·Wf + S·bf)/V
            const int a = t >> 4, p = t & 15;
            float agg = sFanS[a] * b_flr[p];
            #pragma unroll
            for (int f = 0; f < NFEAT; ++f)
                agg += sFanY[a*NFEAT + f] * W_flr[f*NP + p];
            sAgg[t] = agg * (1.0f / (float)NV);
        }
        __syncthreads();
        if (t < 128) {                        // M[a,n] = agg·W_out slice
            const int a = t >> 4, n = t & 15;
            float m = 0.f;
            #pragma unroll
            for (int p = 0; p < NP; ++p)
                m += sAgg[a*NP + p] * W_out[(a*NP + p)*NOUT + n];
            g_M[b * 128 + t] = m;
        }
    }
}

// ---------------------------------------------------------------------------
// k2: PDL secondary (unchanged from R14). Pre-sync: setup; post-sync: g_M/g_ew.
// ---------------------------------------------------------------------------
__global__ __launch_bounds__(256, 4) void k_output(
    const int* __restrict__ num_vertex, const float* __restrict__ b_out,
    float* __restrict__ out)
{
    __shared__ __align__(16) float sM[128];
    __shared__ float sbo[NOUT];

    const int t  = threadIdx.x;
    const int b  = blockIdx.x / S2;
    const int vb = (blockIdx.x % S2) * CHB;
    const int nv = num_vertex[b];            // input tensor: safe pre-sync
    const float4 z = make_float4(0.f, 0.f, 0.f, 0.f);

    const int v0 = vb + t, v1 = vb + 256 + t;
    float4* op0 = (float4*)(out + ((size_t)(b * NV + v0)) * NOUT);
    float4* op1 = (float4*)(out + ((size_t)(b * NV + v1)) * NOUT);

    if (vb >= nv) {
        cudaGridDependencySynchronize();
        op0[0] = z; op0[1] = z; op0[2] = z; op0[3] = z;
        op1[0] = z; op1[1] = z; op1[2] = z; op1[3] = z;
        return;
    }

    if (t < 48 && t >= 32) sbo[t - 32] = b_out[t - 32];   // input: safe pre-sync
    const bool val0 = (v0 < nv), val1 = (v1 < nv);

    cudaGridDependencySynchronize();         // wait for k1's g_M/g_ew

    float4 e00 = z, e01 = z, e10 = z, e11 = z;
    if (val0) {
        const float4* ep = (const float4*)(g_ew + ((size_t)(b * NV + v0)) * NA);
        e00 = ep[0]; e01 = ep[1];
    }
    if (val1) {
        const float4* ep = (const float4*)(g_ew + ((size_t)(b * NV + v1)) * NA);
        e10 = ep[0]; e11 = ep[1];
    }
    if (t < 32) ((float4*)sM)[t] = ((const float4*)g_M)[b * 32 + t];
    __syncthreads();

    const float ew0[8] = {e00.x, e00.y, e00.z, e00.w, e01.x, e01.y, e01.z, e01.w};
    const float ew1[8] = {e10.x, e10.y, e10.z, e10.w, e11.x, e11.y, e11.z, e11.w};

    float4 o0[4], o1[4];
    #pragma unroll
    for (int j = 0; j < 4; ++j) {
        o0[j] = make_float4(sbo[j*4], sbo[j*4+1], sbo[j*4+2], sbo[j*4+3]);
        o1[j] = o0[j];
    }
    #pragma unroll
    for (int a = 0; a < NA; ++a) {
        const float w0 = ew0[a], w1 = ew1[a];
        const float4* mrow = (const float4*)(sM + a * NOUT);
        #pragma unroll
        for (int j = 0; j < 4; ++j) {
            const float4 m = mrow[j];        // one LDS.128 serves both vertices
            o0[j].x += w0 * m.x; o0[j].y += w0 * m.y;
            o0[j].z += w0 * m.z; o0[j].w += w0 * m.w;
            o1[j].x += w1 * m.x; o1[j].y += w1 * m.y;
            o1[j].z += w1 * m.z; o1[j].w += w1 * m.w;
        }
    }

    if (val0) { op0[0]=o0[0]; op0[1]=o0[1]; op0[2]=o0[2]; op0[3]=o0[3]; }
    else      { op0[0]=z;     op0[1]=z;     op0[2]=z;     op0[3]=z;     }
    if (val1) { op1[0]=o1[0]; op1[1]=o1[1]; op1[2]=o1[2]; op1[3]=o1[3]; }
    else      { op1[0]=z;     op1[1]=z;     op1[2]=z;     op1[3]=z;     }
}

extern "C" void kernel_launch(void* const* d_in, const int* in_sizes, int n_in,
                              void* d_out, int out_size) {
    const float* data       = (const float*)d_in[0];
    const int*   num_vertex = (const int*)  d_in[1];
    const float* W_flr      = (const float*)d_in[2];
    const float* b_flr      = (const float*)d_in[3];
    const float* W_s        = (const float*)d_in[4];
    const float* b_s        = (const float*)d_in[5];
    const float* W_out      = (const float*)d_in[6];
    const float* b_out      = (const float*)d_in[7];
    float* out = (float*)d_out;

    k_aggregate<<<GRID1, 256>>>(data, num_vertex, W_flr, b_flr, W_s, b_s, W_out);

    cudaLaunchConfig_t cfg = {};
    cfg.gridDim  = dim3(GRID2, 1, 1);
    cfg.blockDim = dim3(256, 1, 1);
    cudaLaunchAttribute attrs[1];
    attrs[0].id = cudaLaunchAttributeProgrammaticStreamSerialization;
    attrs[0].val.programmaticStreamSerializationAllowed = 1;
    cfg.attrs = attrs;
    cfg.numAttrs = 1;
    cudaLaunchKernelEx(&cfg, k_output, num_vertex, b_out, out);
}